// round 7
// baseline (speedup 1.0000x reference)
#include <cuda_runtime.h>
#include <cstdint>
#include <math.h>

// Problem constants
#define NBINS (1 << 21)          // 128^3
#define NPIX  (4096 * 4096)      // 16,777,216 pixels
#define NFLAGW (NBINS / 32)      // 65536 flag words

// Fixed-point mask accumulation: 24 fractional bits, count in bits [40:64)
#define MASK_SCALE 16777216.0f        // 2^24
#define MASK_INV_SCALE (1.0f / 16777216.0f)
#define MASK_INV_SCALE_D (1.0 / 16777216.0)
#define COUNT_SHIFT 40
#define MASK40 0xFFFFFFFFFFULL        // low 40 bits

// k_out smem bit-table coverage: 57344 words * 32 bins = 1,835,008 bins (224 KB)
#define SMEM_WORDS 57344
#define SMEM_BYTES (SMEM_WORDS * 4)

// Scratch (allocation-free rule: __device__ globals)
__device__ unsigned long long g_hist[NBINS];   // 16 MB, packed count|mask
__device__ float              g_logr[NBINS];   // 8 MB
__device__ int                g_bins[NPIX];    // 64 MB per-pixel bin index
__device__ unsigned int       g_flag[NFLAGW];  // 256 KB bit table
__device__ double             g_sumf_in, g_suml_in, g_avg;
__device__ unsigned long long g_mask_total;

// ---------------------------------------------------------------------------
// K0: clear histogram (vectorized) + scalars
// ---------------------------------------------------------------------------
__global__ void k_clear() {
    int i = blockIdx.x * blockDim.x + threadIdx.x;
    if (i < NBINS / 2) ((ulonglong2*)g_hist)[i] = make_ulonglong2(0ULL, 0ULL);
    if (i == 0) {
        g_sumf_in = 0.0; g_suml_in = 0.0; g_avg = 0.0;
        g_mask_total = 0ULL;
    }
}

// ---------------------------------------------------------------------------
// K1: histogram accumulate + per-pixel bin store. 4 pixels per thread.
// (exact R5 version — proven 174.8us configuration)
// ---------------------------------------------------------------------------
__global__ void __launch_bounds__(256) k_hist(const int* __restrict__ img,
                                              const float* __restrict__ mask) {
    int t = blockIdx.x * blockDim.x + threadIdx.x;   // 0 .. NPIX/4-1
    if (t >= NPIX / 4) return;

    const int4* img4 = (const int4*)img;
    int4 a = img4[t * 3 + 0];
    int4 b = img4[t * 3 + 1];
    int4 c = img4[t * 3 + 2];
    float4 m = ((const float4*)mask)[t];

    int bin0 = ((a.x >> 1) << 14) | ((a.y >> 1) << 7) | (a.z >> 1);
    int bin1 = ((a.w >> 1) << 14) | ((b.x >> 1) << 7) | (b.y >> 1);
    int bin2 = ((b.z >> 1) << 14) | ((b.w >> 1) << 7) | (c.x >> 1);
    int bin3 = ((c.y >> 1) << 14) | ((c.z >> 1) << 7) | (c.w >> 1);

    unsigned long long v0 = (1ULL << COUNT_SHIFT) | (unsigned long long)(m.x * MASK_SCALE + 0.5f);
    unsigned long long v1 = (1ULL << COUNT_SHIFT) | (unsigned long long)(m.y * MASK_SCALE + 0.5f);
    unsigned long long v2 = (1ULL << COUNT_SHIFT) | (unsigned long long)(m.z * MASK_SCALE + 0.5f);
    unsigned long long v3 = (1ULL << COUNT_SHIFT) | (unsigned long long)(m.w * MASK_SCALE + 0.5f);

    atomicAdd(&g_hist[bin0], v0);
    atomicAdd(&g_hist[bin1], v1);
    atomicAdd(&g_hist[bin2], v2);
    atomicAdd(&g_hist[bin3], v3);

    ((int4*)g_bins)[t] = make_int4(bin0, bin1, bin2, bin3);
}

// ---------------------------------------------------------------------------
// K2: sums. Integer-exact mask total (u64), float partials for the input
// arrays (double only at the block-level atomic). Count total == NPIX exactly.
// ---------------------------------------------------------------------------
__global__ void __launch_bounds__(256) k_sums(const float* __restrict__ full_in,
                                              const float* __restrict__ lines_in) {
    int t = blockIdx.x * blockDim.x + threadIdx.x;   // 0 .. NBINS/4-1
    unsigned long long msum = 0ULL;
    float fsum = 0.0f, lsum = 0.0f;
    if (t < NBINS / 4) {
        ulonglong2 h01 = ((const ulonglong2*)g_hist)[t * 2 + 0];
        ulonglong2 h23 = ((const ulonglong2*)g_hist)[t * 2 + 1];
        msum = (h01.x & MASK40) + (h01.y & MASK40) + (h23.x & MASK40) + (h23.y & MASK40);
        float4 f4 = ((const float4*)full_in)[t];
        float4 l4 = ((const float4*)lines_in)[t];
        fsum = (f4.x + f4.y) + (f4.z + f4.w);
        lsum = (l4.x + l4.y) + (l4.z + l4.w);
    }
    for (int o = 16; o > 0; o >>= 1) {
        msum += __shfl_down_sync(0xFFFFFFFFu, msum, o);
        fsum += __shfl_down_sync(0xFFFFFFFFu, fsum, o);
        lsum += __shfl_down_sync(0xFFFFFFFFu, lsum, o);
    }
    __shared__ unsigned long long sm[8];
    __shared__ float sf[8], sl[8];
    int lane = threadIdx.x & 31, wid = threadIdx.x >> 5;
    if (lane == 0) { sm[wid] = msum; sf[wid] = fsum; sl[wid] = lsum; }
    __syncthreads();
    if (wid == 0) {
        msum = (lane < 8) ? sm[lane] : 0ULL;
        fsum = (lane < 8) ? sf[lane] : 0.0f;
        lsum = (lane < 8) ? sl[lane] : 0.0f;
        for (int o = 4; o > 0; o >>= 1) {
            msum += __shfl_down_sync(0xFFFFFFFFu, msum, o);
            fsum += __shfl_down_sync(0xFFFFFFFFu, fsum, o);
            lsum += __shfl_down_sync(0xFFFFFFFFu, lsum, o);
        }
        if (lane == 0) {
            atomicAdd(&g_mask_total, msum);
            atomicAdd(&g_sumf_in, (double)fsum);
            atomicAdd(&g_suml_in, (double)lsum);
        }
    }
}

// ---------------------------------------------------------------------------
// K3: per-bin log ratio + avg. Scalars (C, inv_sl) derived per-block from the
// device totals with the exact double expression (replaces k_prep) —
// deterministic, identical across blocks. lr = logf(l/f) + C.
// ---------------------------------------------------------------------------
__global__ void __launch_bounds__(256) k_logr(const float* __restrict__ full_in,
                                              const float* __restrict__ lines_in) {
    __shared__ float sC, sInvSl;
    if (threadIdx.x == 0) {
        double sfd = g_sumf_in + (double)NPIX + (double)NBINS;
        double sld = g_suml_in + (double)g_mask_total * MASK_INV_SCALE_D
                   + (double)NBINS * 1e-10;
        sC = (float)(log(sfd) - log(sld));
        sInvSl = (float)(1.0 / sld);
    }
    __syncthreads();
    float C = sC, inv_sl = sInvSl;

    int t = blockIdx.x * blockDim.x + threadIdx.x;   // 0 .. NBINS/4-1
    float avg = 0.0f;
    if (t < NBINS / 4) {
        ulonglong2 h01 = ((const ulonglong2*)g_hist)[t * 2 + 0];
        ulonglong2 h23 = ((const ulonglong2*)g_hist)[t * 2 + 1];
        float4 f4 = ((const float4*)full_in)[t];
        float4 l4 = ((const float4*)lines_in)[t];
        unsigned long long hh[4] = {h01.x, h01.y, h23.x, h23.y};
        float ff[4] = {f4.x, f4.y, f4.z, f4.w};
        float ll[4] = {l4.x, l4.y, l4.z, l4.w};
        float lrout[4];
        #pragma unroll
        for (int i = 0; i < 4; i++) {
            float cnt = (float)(hh[i] >> COUNT_SHIFT);
            float ms  = (float)(hh[i] & MASK40) * MASK_INV_SCALE;
            float f = ff[i] + cnt + 1.0f;
            float l = ll[i] + ms + 1e-10f;
            float lr = logf(l / f) + C;
            lrout[i] = lr;
            avg += (l * inv_sl) * lr;
        }
        ((float4*)g_logr)[t] = make_float4(lrout[0], lrout[1], lrout[2], lrout[3]);
    }
    for (int o = 16; o > 0; o >>= 1)
        avg += __shfl_down_sync(0xFFFFFFFFu, avg, o);
    __shared__ float sa[8];
    int lane = threadIdx.x & 31, wid = threadIdx.x >> 5;
    if (lane == 0) sa[wid] = avg;
    __syncthreads();
    if (wid == 0) {
        avg = (lane < 8) ? sa[lane] : 0.0f;
        for (int o = 4; o > 0; o >>= 1)
            avg += __shfl_down_sync(0xFFFFFFFFu, avg, o);
        if (lane == 0) atomicAdd(&g_avg, (double)avg);
    }
}

// ---------------------------------------------------------------------------
// K3b: build 1-bit flag table via ballot
// ---------------------------------------------------------------------------
__global__ void __launch_bounds__(256) k_flag() {
    int i = blockIdx.x * blockDim.x + threadIdx.x;   // 0 .. NBINS-1
    float avgf = (float)g_avg;
    unsigned int m = __ballot_sync(0xFFFFFFFFu, g_logr[i] > avgf);
    if ((i & 31) == 0) g_flag[i >> 5] = m;
}

// ---------------------------------------------------------------------------
// K4: gather. 224KB of the bit table in smem (bins < 1,835,008), rest via L2.
// Persistent: 148 blocks x 1024 threads. (exact R5 version)
// ---------------------------------------------------------------------------
__global__ void __launch_bounds__(1024) k_out(float* __restrict__ out) {
    extern __shared__ unsigned int s_flag[];
    for (int i = threadIdx.x; i < SMEM_WORDS; i += 1024)
        s_flag[i] = g_flag[i];
    __syncthreads();

    int stride = gridDim.x * 1024;
    for (int t = blockIdx.x * 1024 + threadIdx.x; t < NPIX / 4; t += stride) {
        int4 bb = ((const int4*)g_bins)[t];
        float4 o;
        {
            int w = bb.x >> 5, bit = bb.x & 31;
            unsigned int word = (w < SMEM_WORDS) ? s_flag[w] : __ldg(&g_flag[w]);
            o.x = (float)((word >> bit) & 1u);
        }
        {
            int w = bb.y >> 5, bit = bb.y & 31;
            unsigned int word = (w < SMEM_WORDS) ? s_flag[w] : __ldg(&g_flag[w]);
            o.y = (float)((word >> bit) & 1u);
        }
        {
            int w = bb.z >> 5, bit = bb.z & 31;
            unsigned int word = (w < SMEM_WORDS) ? s_flag[w] : __ldg(&g_flag[w]);
            o.z = (float)((word >> bit) & 1u);
        }
        {
            int w = bb.w >> 5, bit = bb.w & 31;
            unsigned int word = (w < SMEM_WORDS) ? s_flag[w] : __ldg(&g_flag[w]);
            o.w = (float)((word >> bit) & 1u);
        }
        ((float4*)out)[t] = o;
    }
}

extern "C" void kernel_launch(void* const* d_in, const int* in_sizes, int n_in,
                              void* d_out, int out_size) {
    const int*   img      = (const int*)d_in[0];
    const float* mask     = (const float*)d_in[1];
    const float* full_in  = (const float*)d_in[2];
    const float* lines_in = (const float*)d_in[3];
    float* out            = (float*)d_out;

    // Idempotent opt-in for 224KB dynamic smem (non-stream call; capture-safe).
    cudaFuncSetAttribute(k_out, cudaFuncAttributeMaxDynamicSharedMemorySize, SMEM_BYTES);

    k_clear<<<(NBINS / 2) / 256, 256>>>();
    k_hist <<<(NPIX / 4) / 256, 256>>>(img, mask);
    k_sums <<<(NBINS / 4) / 256, 256>>>(full_in, lines_in);
    k_logr <<<(NBINS / 4) / 256, 256>>>(full_in, lines_in);
    k_flag <<<NBINS / 256, 256>>>();
    k_out  <<<148, 1024, SMEM_BYTES>>>(out);
}

// round 8
// speedup vs baseline: 1.3770x; 1.3770x over previous
#include <cuda_runtime.h>
#include <cstdint>
#include <math.h>

// Problem constants
#define NBINS (1 << 21)          // 128^3
#define NPIX  (4096 * 4096)      // 16,777,216 pixels
#define NFLAGW (NBINS / 32)      // 65536 flag words
#define NCHUNK (NBINS / 32)      // 65536 32-bin chunks
#define FGRID  148               // fused kernel: one block per SM (co-resident)
#define FWARPS (FGRID * 32)      // 4736 warps
#define CPT    14                // ceil(65536 / 4736) chunks per warp

// Fixed-point mask accumulation: 24 fractional bits, count in bits [40:64)
#define MASK_SCALE 16777216.0f        // 2^24
#define MASK_INV_SCALE (1.0f / 16777216.0f)
#define MASK_INV_SCALE_D (1.0 / 16777216.0)
#define COUNT_SHIFT 40
#define MASK40 0xFFFFFFFFFFULL        // low 40 bits

// k_out smem bit-table coverage: 57344 words * 32 bins = 1,835,008 bins (224 KB)
#define SMEM_WORDS 57344
#define SMEM_BYTES (SMEM_WORDS * 4)

// Scratch (allocation-free rule: __device__ globals)
__device__ unsigned long long g_hist[NBINS];   // 16 MB, packed count|mask
__device__ int                g_bins[NPIX];    // 64 MB per-pixel bin index
__device__ unsigned int       g_flag[NFLAGW];  // 256 KB bit table
__device__ double             g_sumf_in, g_suml_in, g_avg;
__device__ unsigned long long g_mask_total;
__device__ unsigned int       g_bar1, g_bar2;  // software grid barriers

// ---------------------------------------------------------------------------
// K0: clear histogram (vectorized) + scalars + barrier counters
// ---------------------------------------------------------------------------
__global__ void k_clear() {
    int i = blockIdx.x * blockDim.x + threadIdx.x;
    if (i < NBINS / 2) ((ulonglong2*)g_hist)[i] = make_ulonglong2(0ULL, 0ULL);
    if (i == 0) {
        g_sumf_in = 0.0; g_suml_in = 0.0; g_avg = 0.0;
        g_mask_total = 0ULL;
        g_bar1 = 0u; g_bar2 = 0u;
    }
}

// ---------------------------------------------------------------------------
// K1: histogram accumulate + per-pixel bin store. 4 pixels per thread.
// (exact R5 version — proven configuration)
// ---------------------------------------------------------------------------
__global__ void __launch_bounds__(256) k_hist(const int* __restrict__ img,
                                              const float* __restrict__ mask) {
    int t = blockIdx.x * blockDim.x + threadIdx.x;   // 0 .. NPIX/4-1
    if (t >= NPIX / 4) return;

    const int4* img4 = (const int4*)img;
    int4 a = img4[t * 3 + 0];
    int4 b = img4[t * 3 + 1];
    int4 c = img4[t * 3 + 2];
    float4 m = ((const float4*)mask)[t];

    int bin0 = ((a.x >> 1) << 14) | ((a.y >> 1) << 7) | (a.z >> 1);
    int bin1 = ((a.w >> 1) << 14) | ((b.x >> 1) << 7) | (b.y >> 1);
    int bin2 = ((b.z >> 1) << 14) | ((b.w >> 1) << 7) | (c.x >> 1);
    int bin3 = ((c.y >> 1) << 14) | ((c.z >> 1) << 7) | (c.w >> 1);

    unsigned long long v0 = (1ULL << COUNT_SHIFT) | (unsigned long long)(m.x * MASK_SCALE + 0.5f);
    unsigned long long v1 = (1ULL << COUNT_SHIFT) | (unsigned long long)(m.y * MASK_SCALE + 0.5f);
    unsigned long long v2 = (1ULL << COUNT_SHIFT) | (unsigned long long)(m.z * MASK_SCALE + 0.5f);
    unsigned long long v3 = (1ULL << COUNT_SHIFT) | (unsigned long long)(m.w * MASK_SCALE + 0.5f);

    atomicAdd(&g_hist[bin0], v0);
    atomicAdd(&g_hist[bin1], v1);
    atomicAdd(&g_hist[bin2], v2);
    atomicAdd(&g_hist[bin3], v3);

    ((int4*)g_bins)[t] = make_int4(bin0, bin1, bin2, bin3);
}

// ---------------------------------------------------------------------------
// K2 (fused): sums + log-ratio + flag table in one persistent kernel.
// Grid = 148 blocks x 1024 threads (one block per SM -> all co-resident;
// software grid barriers are deadlock-free).
// Warp-uniform chunk map: global warp W handles chunks c = W + j*4736,
// each chunk = 32 consecutive bins (lane = bin within chunk).
// ---------------------------------------------------------------------------
__device__ __forceinline__ void grid_barrier(unsigned int* bar) {
    __syncthreads();
    if (threadIdx.x == 0) {
        __threadfence();
        atomicAdd(bar, 1u);
        while (*((volatile unsigned int*)bar) < FGRID) { }
        __threadfence();
    }
    __syncthreads();
}

__global__ void __launch_bounds__(1024) k_fused(const float* __restrict__ full_in,
                                                const float* __restrict__ lines_in) {
    int tid  = threadIdx.x;
    int lane = tid & 31;
    int wid  = tid >> 5;
    int W    = blockIdx.x * 32 + wid;    // global warp id, 0..4735

    // ---------------- Phase A: sums ----------------
    unsigned long long msum = 0ULL;
    float fsum = 0.0f, lsum = 0.0f;
    #pragma unroll
    for (int j = 0; j < CPT; j++) {
        int c = W + j * FWARPS;
        if (c < NCHUNK) {                 // warp-uniform guard
            int bin = c * 32 + lane;
            unsigned long long h = g_hist[bin];
            msum += (h & MASK40);
            fsum += full_in[bin];
            lsum += lines_in[bin];
        }
    }
    for (int o = 16; o > 0; o >>= 1) {
        msum += __shfl_down_sync(0xFFFFFFFFu, msum, o);
        fsum += __shfl_down_sync(0xFFFFFFFFu, fsum, o);
        lsum += __shfl_down_sync(0xFFFFFFFFu, lsum, o);
    }
    __shared__ unsigned long long sm[32];
    __shared__ float sf[32], sl[32];
    if (lane == 0) { sm[wid] = msum; sf[wid] = fsum; sl[wid] = lsum; }
    __syncthreads();
    if (wid == 0) {
        msum = sm[lane]; fsum = sf[lane]; lsum = sl[lane];
        for (int o = 16; o > 0; o >>= 1) {
            msum += __shfl_down_sync(0xFFFFFFFFu, msum, o);
            fsum += __shfl_down_sync(0xFFFFFFFFu, fsum, o);
            lsum += __shfl_down_sync(0xFFFFFFFFu, lsum, o);
        }
        if (lane == 0) {
            atomicAdd(&g_mask_total, msum);
            atomicAdd(&g_sumf_in, (double)fsum);
            atomicAdd(&g_suml_in, (double)lsum);
        }
    }
    grid_barrier(&g_bar1);

    // Derive scalars (identical doubles in every block)
    __shared__ float sC, sInvSl;
    if (tid == 0) {
        double sfd = *((volatile double*)&g_sumf_in) + (double)NPIX + (double)NBINS;
        double sld = *((volatile double*)&g_suml_in)
                   + (double)(*((volatile unsigned long long*)&g_mask_total)) * MASK_INV_SCALE_D
                   + (double)NBINS * 1e-10;
        sC = (float)(log(sfd) - log(sld));
        sInvSl = (float)(1.0 / sld);
    }
    __syncthreads();
    float C = sC, inv_sl = sInvSl;

    // ---------------- Phase B: log ratios (register-resident) + avg ----------
    float lr[CPT];
    float avg = 0.0f;
    #pragma unroll
    for (int j = 0; j < CPT; j++) {
        int c = W + j * FWARPS;
        if (c < NCHUNK) {                 // L2-hot re-reads
            int bin = c * 32 + lane;
            unsigned long long h = g_hist[bin];
            float cnt = (float)(h >> COUNT_SHIFT);
            float ms  = (float)(h & MASK40) * MASK_INV_SCALE;
            float f = full_in[bin] + cnt + 1.0f;
            float l = lines_in[bin] + ms + 1e-10f;
            float v = logf(l / f) + C;
            lr[j] = v;
            avg += (l * inv_sl) * v;
        } else {
            lr[j] = 0.0f;
        }
    }
    for (int o = 16; o > 0; o >>= 1)
        avg += __shfl_down_sync(0xFFFFFFFFu, avg, o);
    __shared__ float sa[32];
    if (lane == 0) sa[wid] = avg;
    __syncthreads();
    if (wid == 0) {
        avg = sa[lane];
        for (int o = 16; o > 0; o >>= 1)
            avg += __shfl_down_sync(0xFFFFFFFFu, avg, o);
        if (lane == 0) atomicAdd(&g_avg, (double)avg);
    }
    grid_barrier(&g_bar2);

    // ---------------- Phase C: flag bits via ballot ----------------
    float avgf = (float)(*((volatile double*)&g_avg));
    #pragma unroll
    for (int j = 0; j < CPT; j++) {
        int c = W + j * FWARPS;
        if (c < NCHUNK) {                 // warp-uniform: full-warp ballot
            unsigned int m = __ballot_sync(0xFFFFFFFFu, lr[j] > avgf);
            if (lane == 0) g_flag[c] = m;
        }
    }
}

// ---------------------------------------------------------------------------
// K4: gather. 224KB of the bit table in smem (bins < 1,835,008), rest via L2.
// Persistent: 148 blocks x 1024 threads. (exact R5 version)
// ---------------------------------------------------------------------------
__global__ void __launch_bounds__(1024) k_out(float* __restrict__ out) {
    extern __shared__ unsigned int s_flag[];
    for (int i = threadIdx.x; i < SMEM_WORDS; i += 1024)
        s_flag[i] = g_flag[i];
    __syncthreads();

    int stride = gridDim.x * 1024;
    for (int t = blockIdx.x * 1024 + threadIdx.x; t < NPIX / 4; t += stride) {
        int4 bb = ((const int4*)g_bins)[t];
        float4 o;
        {
            int w = bb.x >> 5, bit = bb.x & 31;
            unsigned int word = (w < SMEM_WORDS) ? s_flag[w] : __ldg(&g_flag[w]);
            o.x = (float)((word >> bit) & 1u);
        }
        {
            int w = bb.y >> 5, bit = bb.y & 31;
            unsigned int word = (w < SMEM_WORDS) ? s_flag[w] : __ldg(&g_flag[w]);
            o.y = (float)((word >> bit) & 1u);
        }
        {
            int w = bb.z >> 5, bit = bb.z & 31;
            unsigned int word = (w < SMEM_WORDS) ? s_flag[w] : __ldg(&g_flag[w]);
            o.z = (float)((word >> bit) & 1u);
        }
        {
            int w = bb.w >> 5, bit = bb.w & 31;
            unsigned int word = (w < SMEM_WORDS) ? s_flag[w] : __ldg(&g_flag[w]);
            o.w = (float)((word >> bit) & 1u);
        }
        ((float4*)out)[t] = o;
    }
}

extern "C" void kernel_launch(void* const* d_in, const int* in_sizes, int n_in,
                              void* d_out, int out_size) {
    const int*   img      = (const int*)d_in[0];
    const float* mask     = (const float*)d_in[1];
    const float* full_in  = (const float*)d_in[2];
    const float* lines_in = (const float*)d_in[3];
    float* out            = (float*)d_out;

    // Idempotent opt-in for 224KB dynamic smem (non-stream call; capture-safe).
    cudaFuncSetAttribute(k_out, cudaFuncAttributeMaxDynamicSharedMemorySize, SMEM_BYTES);

    k_clear<<<(NBINS / 2) / 256, 256>>>();
    k_hist <<<(NPIX / 4) / 256, 256>>>(img, mask);
    k_fused<<<FGRID, 1024>>>(full_in, lines_in);
    k_out  <<<148, 1024, SMEM_BYTES>>>(out);
}